// round 10
// baseline (speedup 1.0000x reference)
#include <cuda_runtime.h>
#include <stdint.h>

#define NN 262144
#define NE (4*1024*1024)

// Scratch (device globals — no allocation allowed)
__device__ float g_h0[NN * 16];                 // layer-0 input, padded 9->16 (stride 16)
__device__ float g_hl[4][NN * 32];              // DENSE per-layer outputs (32MB each, L2-resident)
__device__ float g_agg[NN * 32];                // gather output (fully overwritten each layer)
__device__ float g_zpre[NN * 32];               // pre-BN MLP output
__device__ float g_stats[256];                  // per layer: [l*64+c]=sum, [l*64+32+c]=sumsq
__device__ float g_part[2048][64];              // per-block stats partials (from k_node)
// CSR-by-dst scratch
__device__ int g_deg[NN];
__device__ int g_off[NN + 1];
__device__ int g_pos[NN];
__device__ int g_csr[NE];
__device__ int g_bsum[256];
__device__ int g_bsum2[256];

// ---------------------------------------------------------------------------
// init: zero deg, build h0 = cat(x, t, 0-pad) with stride 16
// ---------------------------------------------------------------------------
__global__ void k_init(const float* __restrict__ x, const float* __restrict__ t) {
    int i = blockIdx.x * blockDim.x + threadIdx.x;
    if (i < NN * 16) {
        int n = i >> 4, k = i & 15;
        float v = 0.f;
        if (k < 8) v = x[n * 8 + k];
        else if (k == 8) v = t[0];
        g_h0[i] = v;
    }
    if (i < NN) g_deg[i] = 0;
}

// ---------------------------------------------------------------------------
// CSR build: count, scan (2-level), fill
// ---------------------------------------------------------------------------
__global__ void k_count(const int* __restrict__ dst) {
    int e = blockIdx.x * blockDim.x + threadIdx.x;
    if (e < NE) atomicAdd(&g_deg[dst[e]], 1);
}

__global__ void k_scan1() {   // 256 blocks x 1024 threads: per-block exclusive scan
    __shared__ int s[1024];
    int tid = threadIdx.x;
    int i = blockIdx.x * 1024 + tid;
    int v = g_deg[i];
    s[tid] = v;
    __syncthreads();
#pragma unroll
    for (int off = 1; off < 1024; off <<= 1) {
        int tv = (tid >= off) ? s[tid - off] : 0;
        __syncthreads();
        s[tid] += tv;
        __syncthreads();
    }
    g_off[i] = s[tid] - v;                 // exclusive
    if (tid == 1023) g_bsum[blockIdx.x] = s[1023];
}

__global__ void k_scan2() {   // 1 block x 256 threads: exclusive scan of block sums
    __shared__ int s[256];
    int tid = threadIdx.x;
    int v = g_bsum[tid];
    s[tid] = v;
    __syncthreads();
#pragma unroll
    for (int off = 1; off < 256; off <<= 1) {
        int tv = (tid >= off) ? s[tid - off] : 0;
        __syncthreads();
        s[tid] += tv;
        __syncthreads();
    }
    g_bsum2[tid] = s[tid] - v;
}

__global__ void k_scan3() {
    int i = blockIdx.x * blockDim.x + threadIdx.x;
    if (i < NN) {
        int o = g_off[i] + g_bsum2[i >> 10];
        g_off[i] = o;
        g_pos[i] = o;
    }
    if (i == 0) g_off[NN] = NE;
}

__global__ void k_fill(const int* __restrict__ src, const int* __restrict__ dst) {
    int e = blockIdx.x * blockDim.x + threadIdx.x;
    if (e >= NE) return;
    int slot = atomicAdd(&g_pos[dst[e]], 1);
    g_csr[slot] = src[e];
}

// ---------------------------------------------------------------------------
// gather: chunk-per-thread (sector-perfect: adjacent lanes of a node cover a
// full source row in lockstep). SHIFT=log2(chunks), ST=src row stride floats.
// ---------------------------------------------------------------------------
template<int SHIFT, int ST>
__global__ void __launch_bounds__(256) k_gather(const float* __restrict__ hbase) {
    int idx = blockIdx.x * blockDim.x + threadIdx.x;
    int n = idx >> SHIFT;
    int c = idx & ((1 << SHIFT) - 1);
    if (n >= NN) return;
    int k = g_off[n], end = g_off[n + 1];
    float ax = 0.f, ay = 0.f, az = 0.f, aw = 0.f;
    for (; k + 4 <= end; k += 4) {
        int s0 = g_csr[k], s1 = g_csr[k + 1], s2 = g_csr[k + 2], s3 = g_csr[k + 3];
        float4 v0 = *(const float4*)(hbase + (size_t)s0 * ST + c * 4);
        float4 v1 = *(const float4*)(hbase + (size_t)s1 * ST + c * 4);
        float4 v2 = *(const float4*)(hbase + (size_t)s2 * ST + c * 4);
        float4 v3 = *(const float4*)(hbase + (size_t)s3 * ST + c * 4);
        ax += (v0.x + v1.x) + (v2.x + v3.x);
        ay += (v0.y + v1.y) + (v2.y + v3.y);
        az += (v0.z + v1.z) + (v2.z + v3.z);
        aw += (v0.w + v1.w) + (v2.w + v3.w);
    }
    for (; k < end; k++) {
        int s0 = g_csr[k];
        float4 v0 = *(const float4*)(hbase + (size_t)s0 * ST + c * 4);
        ax += v0.x; ay += v0.y; az += v0.z; aw += v0.w;
    }
    float4 o; o.x = ax; o.y = ay; o.z = az; o.w = aw;
    *(float4*)(g_agg + (size_t)n * 32 + c * 4) = o;
}

// ---------------------------------------------------------------------------
// node MLP + fused BN-stats partials:
// z=(1+eps)h+agg; u=relu(z@W1+b1); v=u@W2+b2 -> g_zpre
// then rotated conflict-free shared reduction of sum/sumsq -> g_part[block]
// ---------------------------------------------------------------------------
template<int K, int KROWS, int HST>
__global__ void __launch_bounds__(128) k_node(
    const float* __restrict__ hprev,
    const float* __restrict__ W1, const float* __restrict__ b1,
    const float* __restrict__ W2, const float* __restrict__ b2,
    const float* __restrict__ eps, int l)
{
    __shared__ float sW1[K * 32];
    __shared__ float sW2[32 * 32];
    __shared__ float sb1[32];
    __shared__ float sb2[32];
    __shared__ float ss[32], sq[32];
    int tid = threadIdx.x;
    for (int i = tid; i < K * 32; i += 128) {
        int k = i >> 5;
        sW1[i] = (k < KROWS) ? W1[i] : 0.f;
    }
    for (int i = tid; i < 1024; i += 128) sW2[i] = W2[i];
    if (tid < 32) { sb1[tid] = b1[tid]; sb2[tid] = b2[tid]; ss[tid] = 0.f; sq[tid] = 0.f; }
    __syncthreads();

    int n = blockIdx.x * 128 + tid;     // grid exactly covers NN
    float e1 = 1.f + eps[l];
    const float* hp = hprev + (size_t)n * HST;
    const float* ap = g_agg + (size_t)n * 32;

    float z[K];
#pragma unroll
    for (int k = 0; k < K; k += 4) {
        float4 h4 = *(const float4*)(hp + k);
        float4 a4 = *(const float4*)(ap + k);
        z[k + 0] = fmaf(e1, h4.x, a4.x);
        z[k + 1] = fmaf(e1, h4.y, a4.y);
        z[k + 2] = fmaf(e1, h4.z, a4.z);
        z[k + 3] = fmaf(e1, h4.w, a4.w);
    }

    float u[32];
#pragma unroll
    for (int j = 0; j < 32; j++) u[j] = sb1[j];
#pragma unroll
    for (int k = 0; k < K; k++) {
        float zk = z[k];
        const float4* w = (const float4*)&sW1[k << 5];
#pragma unroll
        for (int jj = 0; jj < 8; jj++) {
            float4 wv = w[jj];
            u[4 * jj + 0] = fmaf(zk, wv.x, u[4 * jj + 0]);
            u[4 * jj + 1] = fmaf(zk, wv.y, u[4 * jj + 1]);
            u[4 * jj + 2] = fmaf(zk, wv.z, u[4 * jj + 2]);
            u[4 * jj + 3] = fmaf(zk, wv.w, u[4 * jj + 3]);
        }
    }
#pragma unroll
    for (int j = 0; j < 32; j++) u[j] = fmaxf(u[j], 0.f);

    float v[32];
#pragma unroll
    for (int j = 0; j < 32; j++) v[j] = sb2[j];
#pragma unroll
    for (int k = 0; k < 32; k++) {
        float uk = u[k];
        const float4* w = (const float4*)&sW2[k << 5];
#pragma unroll
        for (int jj = 0; jj < 8; jj++) {
            float4 wv = w[jj];
            v[4 * jj + 0] = fmaf(uk, wv.x, v[4 * jj + 0]);
            v[4 * jj + 1] = fmaf(uk, wv.y, v[4 * jj + 1]);
            v[4 * jj + 2] = fmaf(uk, wv.z, v[4 * jj + 2]);
            v[4 * jj + 3] = fmaf(uk, wv.w, v[4 * jj + 3]);
        }
    }

    float* zp = g_zpre + (size_t)n * 32;
#pragma unroll
    for (int jj = 0; jj < 8; jj++) {
        float4 o;
        o.x = v[4 * jj + 0]; o.y = v[4 * jj + 1];
        o.z = v[4 * jj + 2]; o.w = v[4 * jj + 3];
        *(float4*)(zp + 4 * jj) = o;
    }

    // fused stats: rotated channel order -> all lanes hit distinct banks each step
    int rot = tid & 31;
#pragma unroll
    for (int j = 0; j < 32; j++) {
        int c = (rot + j) & 31;
        float vc = v[0];
        // select v[c] without dynamic register indexing penalty: compiler turns
        // this into a 32-way select tree only if needed; use direct index (local
        // array is fully unrolled so v[] stays in regs only with constant idx).
        // Instead iterate channels in rotated order via a second accumulator pass:
        vc = 0.f;
#pragma unroll
        for (int q = 0; q < 32; q++) if (q == c) vc = v[q];
        atomicAdd(&ss[c], vc);
        atomicAdd(&sq[c], vc * vc);
    }
    __syncthreads();
    if (tid < 64) {
        float pv = (tid < 32) ? ss[tid] : sq[tid - 32];
        g_part[blockIdx.x][tid] = pv;
    }
}

// stage B: reduce 2048 x 64 partials -> g_stats[l*64 + c]
__global__ void k_statsB(int l) {
    int tid = threadIdx.x;            // 256 threads
    int c = tid & 63;
    int grp = tid >> 6;               // 0..3
    float s = 0.f;
    for (int i = grp; i < 2048; i += 4) s += g_part[i][c];
    __shared__ float red[4][64];
    red[grp][c] = s;
    __syncthreads();
    if (tid < 64) g_stats[l * 64 + tid] = red[0][tid] + red[1][tid] + red[2][tid] + red[3][tid];
}

// ---------------------------------------------------------------------------
// BN + ReLU -> dense layer output buffer
// ---------------------------------------------------------------------------
__global__ void k_bn(const float* __restrict__ gamma, const float* __restrict__ beta, int l) {
    int i = blockIdx.x * blockDim.x + threadIdx.x;
    if (i >= NN * 32) return;
    int c = i & 31;
    const float inv = 1.0f / (float)NN;
    float mu = g_stats[l * 64 + c] * inv;
    float var = g_stats[l * 64 + 32 + c] * inv - mu * mu;
    float rs = rsqrtf(var + 1e-5f);
    float g = gamma[l * 32 + c], b = beta[l * 32 + c];
    float val = (g_zpre[i] - mu) * rs * g + b;
    g_hl[l][i] = fmaxf(val, 0.f);
}

// ---------------------------------------------------------------------------
// final: new_x = cat(h0..h3) @ lin_W + lin_b; masked write-back (int32 masks)
// ---------------------------------------------------------------------------
__global__ void __launch_bounds__(128) k_final(
    const float* __restrict__ x, const float* __restrict__ linW,
    const float* __restrict__ linb,
    const int* __restrict__ nmask, const int* __restrict__ emask,
    const int* __restrict__ ondp, const int* __restrict__ oedp,
    float* __restrict__ out)
{
    __shared__ float sW[128 * 8];
    __shared__ float sb[8];
    int tid = threadIdx.x;
    for (int i = tid; i < 1024; i += 128) sW[i] = linW[i];
    if (tid < 8) sb[tid] = linb[tid];
    __syncthreads();

    int n = blockIdx.x * 128 + tid;
    if (n >= NN) return;

    float acc[8];
#pragma unroll
    for (int j = 0; j < 8; j++) acc[j] = sb[j];
#pragma unroll
    for (int l = 0; l < 4; l++) {
        const float* cp = &g_hl[l][(size_t)n * 32];
#pragma unroll 8
        for (int k = 0; k < 32; k += 4) {
            float4 cv = *(const float4*)(cp + k);
            float ck[4] = {cv.x, cv.y, cv.z, cv.w};
#pragma unroll
            for (int kk = 0; kk < 4; kk++) {
                const float4* w = (const float4*)&sW[(l * 32 + k + kk) * 8];
                float4 w0 = w[0], w1 = w[1];
                float c0 = ck[kk];
                acc[0] = fmaf(c0, w0.x, acc[0]);
                acc[1] = fmaf(c0, w0.y, acc[1]);
                acc[2] = fmaf(c0, w0.z, acc[2]);
                acc[3] = fmaf(c0, w0.w, acc[3]);
                acc[4] = fmaf(c0, w1.x, acc[4]);
                acc[5] = fmaf(c0, w1.y, acc[5]);
                acc[6] = fmaf(c0, w1.z, acc[6]);
                acc[7] = fmaf(c0, w1.w, acc[7]);
            }
        }
    }

    int ond = ondp[0], oed = oedp[0];
    bool nm = nmask[n] != 0;
    bool em = emask[n] != 0;
#pragma unroll
    for (int j = 0; j < 8; j++) {
        bool take = (j >= 1) && ((nm && j < ond + 1) || (em && j < oed + 1));
        out[(size_t)n * 8 + j] = take ? acc[j] : x[(size_t)n * 8 + j];
    }
}

// ---------------------------------------------------------------------------
extern "C" void kernel_launch(void* const* d_in, const int* in_sizes, int n_in,
                              void* d_out, int out_size) {
    const float* x     = (const float*)d_in[0];
    const float* t     = (const float*)d_in[1];
    const int*   ei    = (const int*)d_in[2];
    const int*   nmask = (const int*)d_in[3];
    const int*   emask = (const int*)d_in[4];
    const int*   ondp  = (const int*)d_in[5];
    const int*   oedp  = (const int*)d_in[6];
    const float* W1f   = (const float*)d_in[7];
    const float* b1f   = (const float*)d_in[8];
    const float* W2f   = (const float*)d_in[9];
    const float* b2f   = (const float*)d_in[10];
    const float* W1r   = (const float*)d_in[11];
    const float* b1r   = (const float*)d_in[12];
    const float* W2r   = (const float*)d_in[13];
    const float* b2r   = (const float*)d_in[14];
    const float* eps   = (const float*)d_in[15];
    const float* gam   = (const float*)d_in[16];
    const float* bet   = (const float*)d_in[17];
    const float* linW  = (const float*)d_in[18];
    const float* linb  = (const float*)d_in[19];
    float* out = (float*)d_out;

    const int* src = ei;
    const int* dst = ei + NE;

    // init + CSR build (once per launch)
    k_init<<<(NN * 16) / 256, 256>>>(x, t);
    k_count<<<NE / 256, 256>>>(dst);
    k_scan1<<<256, 1024>>>();
    k_scan2<<<1, 256>>>();
    k_scan3<<<NN / 256, 256>>>();
    k_fill<<<NE / 256, 256>>>(src, dst);

    float* h0p;  cudaGetSymbolAddress((void**)&h0p, g_h0);
    float* hlp;  cudaGetSymbolAddress((void**)&hlp, g_hl);

    // layer 0 (padded K=12, h0 stride 16; 4 chunk-threads per node)
    k_gather<2, 16><<<(NN * 4) / 256, 256>>>(h0p);
    k_node<12, 9, 16><<<NN / 128, 128>>>(h0p, W1f, b1f, W2f, b2f, eps, 0);
    k_statsB<<<1, 256>>>(0);
    k_bn<<<(NN * 32) / 256, 256>>>(gam, bet, 0);

    // layers 1..3 (dense 32-float rows; 8 chunk-threads per node)
    for (int l = 1; l < 4; l++) {
        const float* hprev = hlp + (size_t)(l - 1) * NN * 32;
        k_gather<3, 32><<<(NN * 8) / 256, 256>>>(hprev);
        k_node<32, 32, 32><<<NN / 128, 128>>>(hprev,
                                              W1r + (l - 1) * 1024, b1r + (l - 1) * 32,
                                              W2r + (l - 1) * 1024, b2r + (l - 1) * 32,
                                              eps, l);
        k_statsB<<<1, 256>>>(l);
        k_bn<<<(NN * 32) / 256, 256>>>(gam, bet, l);
    }

    k_final<<<NN / 128, 128>>>(x, linW, linb, nmask, emask, ondp, oedp, out);
}

// round 11
// speedup vs baseline: 1.5100x; 1.5100x over previous
#include <cuda_runtime.h>
#include <cuda_fp16.h>
#include <stdint.h>

#define NN 262144
#define NE (4*1024*1024)

// Scratch (device globals — no allocation allowed)
__device__ __half g_h0[NN * 16];                // layer-0 input, half, padded 9->16 (32B rows)
__device__ __half g_hl[4][NN * 32];             // DENSE per-layer outputs, half (64B rows)
__device__ float  g_agg[NN * 32];               // gather output, fp32
__device__ float  g_zpre[NN * 32];              // pre-BN MLP output, fp32
__device__ float  g_stats[256];                 // per layer: [l*64+c]=sum, [l*64+32+c]=sumsq
// CSR-by-dst scratch
__device__ int g_deg[NN];
__device__ int g_off[NN + 1];
__device__ int g_pos[NN];
__device__ int g_csr[NE];
__device__ int g_bsum[256];
__device__ int g_bsum2[256];

// accumulate 8 halfs (one uint4) into 8 float accumulators
__device__ __forceinline__ void acc8(float* a, uint4 v) {
    const __half2* h = (const __half2*)&v;
#pragma unroll
    for (int q = 0; q < 4; q++) {
        float2 f = __half22float2(h[q]);
        a[2 * q + 0] += f.x;
        a[2 * q + 1] += f.y;
    }
}

// ---------------------------------------------------------------------------
// init: zero deg + stats, build h0 = cat(x, t, 0-pad) as half, stride 16
// ---------------------------------------------------------------------------
__global__ void k_init(const float* __restrict__ x, const float* __restrict__ t) {
    int i = blockIdx.x * blockDim.x + threadIdx.x;
    if (i < NN * 16) {
        int n = i >> 4, k = i & 15;
        float v = 0.f;
        if (k < 8) v = x[n * 8 + k];
        else if (k == 8) v = t[0];
        g_h0[i] = __float2half(v);
    }
    if (i < NN) g_deg[i] = 0;
    if (i < 256) g_stats[i] = 0.f;
}

// ---------------------------------------------------------------------------
// CSR build: count, scan (2-level), fill
// ---------------------------------------------------------------------------
__global__ void k_count(const int* __restrict__ dst) {
    int e = blockIdx.x * blockDim.x + threadIdx.x;
    if (e < NE) atomicAdd(&g_deg[dst[e]], 1);
}

__global__ void k_scan1() {   // 256 blocks x 1024 threads: per-block exclusive scan
    __shared__ int s[1024];
    int tid = threadIdx.x;
    int i = blockIdx.x * 1024 + tid;
    int v = g_deg[i];
    s[tid] = v;
    __syncthreads();
#pragma unroll
    for (int off = 1; off < 1024; off <<= 1) {
        int tv = (tid >= off) ? s[tid - off] : 0;
        __syncthreads();
        s[tid] += tv;
        __syncthreads();
    }
    g_off[i] = s[tid] - v;                 // exclusive
    if (tid == 1023) g_bsum[blockIdx.x] = s[1023];
}

__global__ void k_scan2() {   // 1 block x 256 threads: exclusive scan of block sums
    __shared__ int s[256];
    int tid = threadIdx.x;
    int v = g_bsum[tid];
    s[tid] = v;
    __syncthreads();
#pragma unroll
    for (int off = 1; off < 256; off <<= 1) {
        int tv = (tid >= off) ? s[tid - off] : 0;
        __syncthreads();
        s[tid] += tv;
        __syncthreads();
    }
    g_bsum2[tid] = s[tid] - v;
}

__global__ void k_scan3() {
    int i = blockIdx.x * blockDim.x + threadIdx.x;
    if (i < NN) {
        int o = g_off[i] + g_bsum2[i >> 10];
        g_off[i] = o;
        g_pos[i] = o;
    }
    if (i == 0) g_off[NN] = NE;
}

__global__ void k_fill(const int* __restrict__ src, const int* __restrict__ dst) {
    int e = blockIdx.x * blockDim.x + threadIdx.x;
    if (e >= NE) return;
    int slot = atomicAdd(&g_pos[dst[e]], 1);
    g_csr[slot] = src[e];
}

// ---------------------------------------------------------------------------
// gather (half source): chunk-per-thread, each chunk = 8 channels (one uint4
// = 16B of halfs). SHIFT=log2(chunks/node), ROWH=row stride in halfs.
// Adjacent chunk-lanes of a node cover the full row in lockstep ->
// sector-perfect (rows are 32B/64B aligned).
// ---------------------------------------------------------------------------
template<int SHIFT, int ROWH>
__global__ void __launch_bounds__(256) k_gatherH(const __half* __restrict__ hbase) {
    int idx = blockIdx.x * blockDim.x + threadIdx.x;
    int n = idx >> SHIFT;
    int c = idx & ((1 << SHIFT) - 1);
    if (n >= NN) return;
    int k = g_off[n], end = g_off[n + 1];
    float a[8];
#pragma unroll
    for (int q = 0; q < 8; q++) a[q] = 0.f;
    for (; k + 4 <= end; k += 4) {
        int s0 = g_csr[k], s1 = g_csr[k + 1], s2 = g_csr[k + 2], s3 = g_csr[k + 3];
        uint4 v0 = *((const uint4*)(hbase + (size_t)s0 * ROWH) + c);
        uint4 v1 = *((const uint4*)(hbase + (size_t)s1 * ROWH) + c);
        uint4 v2 = *((const uint4*)(hbase + (size_t)s2 * ROWH) + c);
        uint4 v3 = *((const uint4*)(hbase + (size_t)s3 * ROWH) + c);
        acc8(a, v0); acc8(a, v1); acc8(a, v2); acc8(a, v3);
    }
    for (; k < end; k++) {
        int s0 = g_csr[k];
        uint4 v0 = *((const uint4*)(hbase + (size_t)s0 * ROWH) + c);
        acc8(a, v0);
    }
    float* ap = g_agg + (size_t)n * 32 + c * 8;
    float4 o0; o0.x = a[0]; o0.y = a[1]; o0.z = a[2]; o0.w = a[3];
    float4 o1; o1.x = a[4]; o1.y = a[5]; o1.z = a[6]; o1.w = a[7];
    *(float4*)(ap + 0) = o0;
    *(float4*)(ap + 4) = o1;
}

// ---------------------------------------------------------------------------
// node MLP: z=(1+eps)h+agg; u=relu(z@W1+b1); v=u@W2+b2 -> g_zpre
// hprev is a dense half buffer with row stride HSTH halfs.
// ---------------------------------------------------------------------------
template<int K, int KROWS, int HSTH>
__global__ void __launch_bounds__(128) k_node(
    const __half* __restrict__ hprev,
    const float* __restrict__ W1, const float* __restrict__ b1,
    const float* __restrict__ W2, const float* __restrict__ b2,
    const float* __restrict__ eps, int l)
{
    __shared__ float sW1[K * 32];
    __shared__ float sW2[32 * 32];
    __shared__ float sb1[32];
    __shared__ float sb2[32];
    int tid = threadIdx.x;
    for (int i = tid; i < K * 32; i += 128) {
        int k = i >> 5;
        sW1[i] = (k < KROWS) ? W1[i] : 0.f;
    }
    for (int i = tid; i < 1024; i += 128) sW2[i] = W2[i];
    if (tid < 32) { sb1[tid] = b1[tid]; sb2[tid] = b2[tid]; }
    __syncthreads();

    int n = blockIdx.x * 128 + tid;
    if (n >= NN) return;
    float e1 = 1.f + eps[l];
    const uint4* hp4 = (const uint4*)(hprev + (size_t)n * HSTH);
    const float* ap = g_agg + (size_t)n * 32;

    float hf[HSTH];
#pragma unroll
    for (int q = 0; q < HSTH / 8; q++) {
        uint4 r = hp4[q];
        const __half2* h2 = (const __half2*)&r;
#pragma unroll
        for (int p = 0; p < 4; p++) {
            float2 f = __half22float2(h2[p]);
            hf[q * 8 + 2 * p + 0] = f.x;
            hf[q * 8 + 2 * p + 1] = f.y;
        }
    }

    float z[K];
#pragma unroll
    for (int k = 0; k < K; k += 4) {
        float4 a4 = *(const float4*)(ap + k);
        z[k + 0] = fmaf(e1, hf[k + 0], a4.x);
        z[k + 1] = fmaf(e1, hf[k + 1], a4.y);
        z[k + 2] = fmaf(e1, hf[k + 2], a4.z);
        z[k + 3] = fmaf(e1, hf[k + 3], a4.w);
    }

    float u[32];
#pragma unroll
    for (int j = 0; j < 32; j++) u[j] = sb1[j];
#pragma unroll
    for (int k = 0; k < K; k++) {
        float zk = z[k];
        const float4* w = (const float4*)&sW1[k << 5];
#pragma unroll
        for (int jj = 0; jj < 8; jj++) {
            float4 wv = w[jj];
            u[4 * jj + 0] = fmaf(zk, wv.x, u[4 * jj + 0]);
            u[4 * jj + 1] = fmaf(zk, wv.y, u[4 * jj + 1]);
            u[4 * jj + 2] = fmaf(zk, wv.z, u[4 * jj + 2]);
            u[4 * jj + 3] = fmaf(zk, wv.w, u[4 * jj + 3]);
        }
    }
#pragma unroll
    for (int j = 0; j < 32; j++) u[j] = fmaxf(u[j], 0.f);

    float v[32];
#pragma unroll
    for (int j = 0; j < 32; j++) v[j] = sb2[j];
#pragma unroll
    for (int k = 0; k < 32; k++) {
        float uk = u[k];
        const float4* w = (const float4*)&sW2[k << 5];
#pragma unroll
        for (int jj = 0; jj < 8; jj++) {
            float4 wv = w[jj];
            v[4 * jj + 0] = fmaf(uk, wv.x, v[4 * jj + 0]);
            v[4 * jj + 1] = fmaf(uk, wv.y, v[4 * jj + 1]);
            v[4 * jj + 2] = fmaf(uk, wv.z, v[4 * jj + 2]);
            v[4 * jj + 3] = fmaf(uk, wv.w, v[4 * jj + 3]);
        }
    }

    float* zp = g_zpre + (size_t)n * 32;
#pragma unroll
    for (int jj = 0; jj < 8; jj++) {
        float4 o;
        o.x = v[4 * jj + 0]; o.y = v[4 * jj + 1];
        o.z = v[4 * jj + 2]; o.w = v[4 * jj + 3];
        *(float4*)(zp + 4 * jj) = o;
    }
}

// ---------------------------------------------------------------------------
// BN stats: lane c owns channel c (coalesced), shared + global atomics
// ---------------------------------------------------------------------------
__global__ void k_stats(int l) {
    int lane = threadIdx.x & 31;
    int warpId = (blockIdx.x * blockDim.x + threadIdx.x) >> 5;
    int nwarps = (gridDim.x * blockDim.x) >> 5;
    float s = 0.f, q = 0.f;
    for (int n = warpId; n < NN; n += nwarps) {
        float v = g_zpre[(size_t)n * 32 + lane];
        s += v;
        q += v * v;
    }
    __shared__ float ss[32], sq[32];
    if (threadIdx.x < 32) { ss[threadIdx.x] = 0.f; sq[threadIdx.x] = 0.f; }
    __syncthreads();
    atomicAdd(&ss[lane], s);
    atomicAdd(&sq[lane], q);
    __syncthreads();
    if (threadIdx.x < 32) {
        atomicAdd(&g_stats[l * 64 + threadIdx.x], ss[threadIdx.x]);
        atomicAdd(&g_stats[l * 64 + 32 + threadIdx.x], sq[threadIdx.x]);
    }
}

// ---------------------------------------------------------------------------
// BN + ReLU -> dense half layer buffer
// ---------------------------------------------------------------------------
__global__ void k_bn(const float* __restrict__ gamma, const float* __restrict__ beta, int l) {
    int i = blockIdx.x * blockDim.x + threadIdx.x;
    if (i >= NN * 32) return;
    int c = i & 31;
    const float inv = 1.0f / (float)NN;
    float mu = g_stats[l * 64 + c] * inv;
    float var = g_stats[l * 64 + 32 + c] * inv - mu * mu;
    float rs = rsqrtf(var + 1e-5f);
    float g = gamma[l * 32 + c], b = beta[l * 32 + c];
    float val = (g_zpre[i] - mu) * rs * g + b;
    g_hl[l][i] = __float2half(fmaxf(val, 0.f));
}

// ---------------------------------------------------------------------------
// final: new_x = cat(h0..h3) @ lin_W + lin_b; masked write-back (int32 masks)
// ---------------------------------------------------------------------------
__global__ void __launch_bounds__(128) k_final(
    const float* __restrict__ x, const float* __restrict__ linW,
    const float* __restrict__ linb,
    const int* __restrict__ nmask, const int* __restrict__ emask,
    const int* __restrict__ ondp, const int* __restrict__ oedp,
    float* __restrict__ out)
{
    __shared__ float sW[128 * 8];
    __shared__ float sb[8];
    int tid = threadIdx.x;
    for (int i = tid; i < 1024; i += 128) sW[i] = linW[i];
    if (tid < 8) sb[tid] = linb[tid];
    __syncthreads();

    int n = blockIdx.x * 128 + tid;
    if (n >= NN) return;

    float acc[8];
#pragma unroll
    for (int j = 0; j < 8; j++) acc[j] = sb[j];
#pragma unroll
    for (int l = 0; l < 4; l++) {
        const uint4* cp4 = (const uint4*)(&g_hl[l][(size_t)n * 32]);
#pragma unroll
        for (int q = 0; q < 4; q++) {           // 8 channels per uint4
            uint4 r = cp4[q];
            const __half2* h2 = (const __half2*)&r;
#pragma unroll
            for (int p = 0; p < 4; p++) {
                float2 f = __half22float2(h2[p]);
                float c0 = f.x, c1 = f.y;
                int kk = l * 32 + q * 8 + 2 * p;
                const float4* w0 = (const float4*)&sW[kk * 8];
                const float4* w1 = (const float4*)&sW[(kk + 1) * 8];
                float4 a0 = w0[0], b0 = w0[1], a1 = w1[0], b1 = w1[1];
                acc[0] = fmaf(c0, a0.x, acc[0]); acc[0] = fmaf(c1, a1.x, acc[0]);
                acc[1] = fmaf(c0, a0.y, acc[1]); acc[1] = fmaf(c1, a1.y, acc[1]);
                acc[2] = fmaf(c0, a0.z, acc[2]); acc[2] = fmaf(c1, a1.z, acc[2]);
                acc[3] = fmaf(c0, a0.w, acc[3]); acc[3] = fmaf(c1, a1.w, acc[3]);
                acc[4] = fmaf(c0, b0.x, acc[4]); acc[4] = fmaf(c1, b1.x, acc[4]);
                acc[5] = fmaf(c0, b0.y, acc[5]); acc[5] = fmaf(c1, b1.y, acc[5]);
                acc[6] = fmaf(c0, b0.z, acc[6]); acc[6] = fmaf(c1, b1.z, acc[6]);
                acc[7] = fmaf(c0, b0.w, acc[7]); acc[7] = fmaf(c1, b1.w, acc[7]);
            }
        }
    }

    int ond = ondp[0], oed = oedp[0];
    bool nm = nmask[n] != 0;
    bool em = emask[n] != 0;
#pragma unroll
    for (int j = 0; j < 8; j++) {
        bool take = (j >= 1) && ((nm && j < ond + 1) || (em && j < oed + 1));
        out[(size_t)n * 8 + j] = take ? acc[j] : x[(size_t)n * 8 + j];
    }
}

// ---------------------------------------------------------------------------
extern "C" void kernel_launch(void* const* d_in, const int* in_sizes, int n_in,
                              void* d_out, int out_size) {
    const float* x     = (const float*)d_in[0];
    const float* t     = (const float*)d_in[1];
    const int*   ei    = (const int*)d_in[2];
    const int*   nmask = (const int*)d_in[3];
    const int*   emask = (const int*)d_in[4];
    const int*   ondp  = (const int*)d_in[5];
    const int*   oedp  = (const int*)d_in[6];
    const float* W1f   = (const float*)d_in[7];
    const float* b1f   = (const float*)d_in[8];
    const float* W2f   = (const float*)d_in[9];
    const float* b2f   = (const float*)d_in[10];
    const float* W1r   = (const float*)d_in[11];
    const float* b1r   = (const float*)d_in[12];
    const float* W2r   = (const float*)d_in[13];
    const float* b2r   = (const float*)d_in[14];
    const float* eps   = (const float*)d_in[15];
    const float* gam   = (const float*)d_in[16];
    const float* bet   = (const float*)d_in[17];
    const float* linW  = (const float*)d_in[18];
    const float* linb  = (const float*)d_in[19];
    float* out = (float*)d_out;

    const int* src = ei;
    const int* dst = ei + NE;

    // init + CSR build (once per launch)
    k_init<<<(NN * 16) / 256, 256>>>(x, t);
    k_count<<<NE / 256, 256>>>(dst);
    k_scan1<<<256, 1024>>>();
    k_scan2<<<1, 256>>>();
    k_scan3<<<NN / 256, 256>>>();
    k_fill<<<NE / 256, 256>>>(src, dst);

    __half* h0p;  cudaGetSymbolAddress((void**)&h0p, g_h0);
    __half* hlp;  cudaGetSymbolAddress((void**)&hlp, g_hl);

    // layer 0 (padded K=12, h0 stride 16 halfs = 32B rows; 2 chunk-threads/node)
    k_gatherH<1, 16><<<(NN * 2) / 256, 256>>>(h0p);
    k_node<12, 9, 16><<<NN / 128, 128>>>(h0p, W1f, b1f, W2f, b2f, eps, 0);
    k_stats<<<1024, 256>>>(0);
    k_bn<<<(NN * 32) / 256, 256>>>(gam, bet, 0);

    // layers 1..3 (64B half rows; 4 chunk-threads per node)
    for (int l = 1; l < 4; l++) {
        const __half* hprev = hlp + (size_t)(l - 1) * NN * 32;
        k_gatherH<2, 32><<<(NN * 4) / 256, 256>>>(hprev);
        k_node<32, 32, 32><<<NN / 128, 128>>>(hprev,
                                              W1r + (l - 1) * 1024, b1r + (l - 1) * 32,
                                              W2r + (l - 1) * 1024, b2r + (l - 1) * 32,
                                              eps, l);
        k_stats<<<1024, 256>>>(l);
        k_bn<<<(NN * 32) / 256, 256>>>(gam, bet, l);
    }

    k_final<<<NN / 128, 128>>>(x, linW, linb, nmask, emask, ondp, oedp, out);
}

// round 12
// speedup vs baseline: 1.5210x; 1.0073x over previous
#include <cuda_runtime.h>
#include <cuda_fp16.h>
#include <stdint.h>

#define NN 262144
#define NE (4*1024*1024)

typedef unsigned long long ull;

// Scratch (device globals — no allocation allowed)
__device__ __half g_h0[NN * 16];                // layer-0 input, half, padded 9->16 (32B rows)
__device__ __half g_hl[4][NN * 32];             // DENSE per-layer outputs, half (64B rows)
__device__ float  g_agg[NN * 32];               // gather output, fp32
__device__ float  g_zpre[NN * 32];              // pre-BN MLP output, fp32
__device__ float  g_stats[256];                 // per layer: [l*64+c]=sum, [l*64+32+c]=sumsq
// CSR-by-dst scratch
__device__ int g_deg[NN];
__device__ int g_off[NN + 1];
__device__ int g_pos[NN];
__device__ int g_csr[NE];
__device__ int g_bsum[256];
__device__ int g_bsum2[256];

// packed f32x2 helpers (FFMA2 is PTX-only on sm_103a; ptxas never auto-fuses)
__device__ __forceinline__ ull pk2(float a, float b) {
    ull r; asm("mov.b64 %0,{%1,%2};" : "=l"(r) : "f"(a), "f"(b)); return r;
}
__device__ __forceinline__ void upk2(ull v, float& a, float& b) {
    asm("mov.b64 {%0,%1},%2;" : "=f"(a), "=f"(b) : "l"(v));
}
__device__ __forceinline__ ull fma2(ull a, ull b, ull c) {
    ull d; asm("fma.rn.f32x2 %0,%1,%2,%3;" : "=l"(d) : "l"(a), "l"(b), "l"(c)); return d;
}

// accumulate 8 halfs (one uint4) into 8 float accumulators
__device__ __forceinline__ void acc8(float* a, uint4 v) {
    const __half2* h = (const __half2*)&v;
#pragma unroll
    for (int q = 0; q < 4; q++) {
        float2 f = __half22float2(h[q]);
        a[2 * q + 0] += f.x;
        a[2 * q + 1] += f.y;
    }
}

// ---------------------------------------------------------------------------
// init: zero deg + stats, build h0 = cat(x, t, 0-pad) as half, stride 16
// ---------------------------------------------------------------------------
__global__ void k_init(const float* __restrict__ x, const float* __restrict__ t) {
    int i = blockIdx.x * blockDim.x + threadIdx.x;
    if (i < NN * 16) {
        int n = i >> 4, k = i & 15;
        float v = 0.f;
        if (k < 8) v = x[n * 8 + k];
        else if (k == 8) v = t[0];
        g_h0[i] = __float2half(v);
    }
    if (i < NN) g_deg[i] = 0;
    if (i < 256) g_stats[i] = 0.f;
}

// ---------------------------------------------------------------------------
// CSR build: count, scan (2-level), fill
// ---------------------------------------------------------------------------
__global__ void k_count(const int* __restrict__ dst) {
    int e = blockIdx.x * blockDim.x + threadIdx.x;
    if (e < NE) atomicAdd(&g_deg[dst[e]], 1);
}

__global__ void k_scan1() {   // 256 blocks x 1024 threads: per-block exclusive scan
    __shared__ int s[1024];
    int tid = threadIdx.x;
    int i = blockIdx.x * 1024 + tid;
    int v = g_deg[i];
    s[tid] = v;
    __syncthreads();
#pragma unroll
    for (int off = 1; off < 1024; off <<= 1) {
        int tv = (tid >= off) ? s[tid - off] : 0;
        __syncthreads();
        s[tid] += tv;
        __syncthreads();
    }
    g_off[i] = s[tid] - v;                 // exclusive
    if (tid == 1023) g_bsum[blockIdx.x] = s[1023];
}

__global__ void k_scan2() {   // 1 block x 256 threads: exclusive scan of block sums
    __shared__ int s[256];
    int tid = threadIdx.x;
    int v = g_bsum[tid];
    s[tid] = v;
    __syncthreads();
#pragma unroll
    for (int off = 1; off < 256; off <<= 1) {
        int tv = (tid >= off) ? s[tid - off] : 0;
        __syncthreads();
        s[tid] += tv;
        __syncthreads();
    }
    g_bsum2[tid] = s[tid] - v;
}

__global__ void k_scan3() {
    int i = blockIdx.x * blockDim.x + threadIdx.x;
    if (i < NN) {
        int o = g_off[i] + g_bsum2[i >> 10];
        g_off[i] = o;
        g_pos[i] = o;
    }
    if (i == 0) g_off[NN] = NE;
}

__global__ void k_fill(const int* __restrict__ src, const int* __restrict__ dst) {
    int e = blockIdx.x * blockDim.x + threadIdx.x;
    if (e >= NE) return;
    int slot = atomicAdd(&g_pos[dst[e]], 1);
    g_csr[slot] = src[e];
}

// ---------------------------------------------------------------------------
// gather (half source): chunk-per-thread, each chunk = 8 channels (one uint4
// = 16B of halfs). SHIFT=log2(chunks/node), ROWH=row stride in halfs.
// ---------------------------------------------------------------------------
template<int SHIFT, int ROWH>
__global__ void __launch_bounds__(256) k_gatherH(const __half* __restrict__ hbase) {
    int idx = blockIdx.x * blockDim.x + threadIdx.x;
    int n = idx >> SHIFT;
    int c = idx & ((1 << SHIFT) - 1);
    if (n >= NN) return;
    int k = g_off[n], end = g_off[n + 1];
    float a[8];
#pragma unroll
    for (int q = 0; q < 8; q++) a[q] = 0.f;
    for (; k + 4 <= end; k += 4) {
        int s0 = g_csr[k], s1 = g_csr[k + 1], s2 = g_csr[k + 2], s3 = g_csr[k + 3];
        uint4 v0 = *((const uint4*)(hbase + (size_t)s0 * ROWH) + c);
        uint4 v1 = *((const uint4*)(hbase + (size_t)s1 * ROWH) + c);
        uint4 v2 = *((const uint4*)(hbase + (size_t)s2 * ROWH) + c);
        uint4 v3 = *((const uint4*)(hbase + (size_t)s3 * ROWH) + c);
        acc8(a, v0); acc8(a, v1); acc8(a, v2); acc8(a, v3);
    }
    for (; k < end; k++) {
        int s0 = g_csr[k];
        uint4 v0 = *((const uint4*)(hbase + (size_t)s0 * ROWH) + c);
        acc8(a, v0);
    }
    float* ap = g_agg + (size_t)n * 32 + c * 8;
    float4 o0; o0.x = a[0]; o0.y = a[1]; o0.z = a[2]; o0.w = a[3];
    float4 o1; o1.x = a[4]; o1.y = a[5]; o1.z = a[6]; o1.w = a[7];
    *(float4*)(ap + 0) = o0;
    *(float4*)(ap + 4) = o1;
}

// ---------------------------------------------------------------------------
// node MLP (packed f32x2 GEMMs): z=(1+eps)h+agg; u=relu(z@W1+b1);
// v=u@W2+b2 -> g_zpre. hprev is a dense half buffer, row stride HSTH halfs.
// ---------------------------------------------------------------------------
template<int K, int KROWS, int HSTH>
__global__ void __launch_bounds__(128) k_node(
    const __half* __restrict__ hprev,
    const float* __restrict__ W1, const float* __restrict__ b1,
    const float* __restrict__ W2, const float* __restrict__ b2,
    const float* __restrict__ eps, int l)
{
    __shared__ __align__(16) float sW1[K * 32];
    __shared__ __align__(16) float sW2[32 * 32];
    __shared__ __align__(16) float sb1[32];
    __shared__ __align__(16) float sb2[32];
    int tid = threadIdx.x;
    for (int i = tid; i < K * 32; i += 128) {
        int k = i >> 5;
        sW1[i] = (k < KROWS) ? W1[i] : 0.f;
    }
    for (int i = tid; i < 1024; i += 128) sW2[i] = W2[i];
    if (tid < 32) { sb1[tid] = b1[tid]; sb2[tid] = b2[tid]; }
    __syncthreads();

    int n = blockIdx.x * 128 + tid;
    if (n >= NN) return;
    float e1 = 1.f + eps[l];
    const uint4* hp4 = (const uint4*)(hprev + (size_t)n * HSTH);
    const float* ap = g_agg + (size_t)n * 32;

    float hf[HSTH];
#pragma unroll
    for (int q = 0; q < HSTH / 8; q++) {
        uint4 r = hp4[q];
        const __half2* h2 = (const __half2*)&r;
#pragma unroll
        for (int p = 0; p < 4; p++) {
            float2 f = __half22float2(h2[p]);
            hf[q * 8 + 2 * p + 0] = f.x;
            hf[q * 8 + 2 * p + 1] = f.y;
        }
    }

    float z[K];
#pragma unroll
    for (int k = 0; k < K; k += 4) {
        float4 a4 = *(const float4*)(ap + k);
        z[k + 0] = fmaf(e1, hf[k + 0], a4.x);
        z[k + 1] = fmaf(e1, hf[k + 1], a4.y);
        z[k + 2] = fmaf(e1, hf[k + 2], a4.z);
        z[k + 3] = fmaf(e1, hf[k + 3], a4.w);
    }

    // GEMM1 (packed pairs of output channels)
    ull u2[16];
    const ull* b1p = (const ull*)sb1;
#pragma unroll
    for (int jj = 0; jj < 16; jj++) u2[jj] = b1p[jj];
#pragma unroll
    for (int k = 0; k < K; k++) {
        ull zz = pk2(z[k], z[k]);
        const ulonglong2* w = (const ulonglong2*)&sW1[k << 5];
#pragma unroll
        for (int jj = 0; jj < 8; jj++) {
            ulonglong2 wv = w[jj];
            u2[2 * jj + 0] = fma2(zz, wv.x, u2[2 * jj + 0]);
            u2[2 * jj + 1] = fma2(zz, wv.y, u2[2 * jj + 1]);
        }
    }
    float u[32];
#pragma unroll
    for (int jj = 0; jj < 16; jj++) upk2(u2[jj], u[2 * jj], u[2 * jj + 1]);
#pragma unroll
    for (int j = 0; j < 32; j++) u[j] = fmaxf(u[j], 0.f);

    // GEMM2 (packed pairs)
    ull v2[16];
    const ull* b2p = (const ull*)sb2;
#pragma unroll
    for (int jj = 0; jj < 16; jj++) v2[jj] = b2p[jj];
#pragma unroll
    for (int k = 0; k < 32; k++) {
        ull uu = pk2(u[k], u[k]);
        const ulonglong2* w = (const ulonglong2*)&sW2[k << 5];
#pragma unroll
        for (int jj = 0; jj < 8; jj++) {
            ulonglong2 wv = w[jj];
            v2[2 * jj + 0] = fma2(uu, wv.x, v2[2 * jj + 0]);
            v2[2 * jj + 1] = fma2(uu, wv.y, v2[2 * jj + 1]);
        }
    }

    ulonglong2* zp = (ulonglong2*)(g_zpre + (size_t)n * 32);
#pragma unroll
    for (int q = 0; q < 8; q++) {
        ulonglong2 o; o.x = v2[2 * q]; o.y = v2[2 * q + 1];
        zp[q] = o;
    }
}

// ---------------------------------------------------------------------------
// BN stats: lane c owns channel c (coalesced), shared + global atomics
// ---------------------------------------------------------------------------
__global__ void k_stats(int l) {
    int lane = threadIdx.x & 31;
    int warpId = (blockIdx.x * blockDim.x + threadIdx.x) >> 5;
    int nwarps = (gridDim.x * blockDim.x) >> 5;
    float s = 0.f, q = 0.f;
    for (int n = warpId; n < NN; n += nwarps) {
        float v = g_zpre[(size_t)n * 32 + lane];
        s += v;
        q += v * v;
    }
    __shared__ float ss[32], sq[32];
    if (threadIdx.x < 32) { ss[threadIdx.x] = 0.f; sq[threadIdx.x] = 0.f; }
    __syncthreads();
    atomicAdd(&ss[lane], s);
    atomicAdd(&sq[lane], q);
    __syncthreads();
    if (threadIdx.x < 32) {
        atomicAdd(&g_stats[l * 64 + threadIdx.x], ss[threadIdx.x]);
        atomicAdd(&g_stats[l * 64 + 32 + threadIdx.x], sq[threadIdx.x]);
    }
}

// ---------------------------------------------------------------------------
// BN + ReLU -> dense half layer buffer
// ---------------------------------------------------------------------------
__global__ void k_bn(const float* __restrict__ gamma, const float* __restrict__ beta, int l) {
    int i = blockIdx.x * blockDim.x + threadIdx.x;
    if (i >= NN * 32) return;
    int c = i & 31;
    const float inv = 1.0f / (float)NN;
    float mu = g_stats[l * 64 + c] * inv;
    float var = g_stats[l * 64 + 32 + c] * inv - mu * mu;
    float rs = rsqrtf(var + 1e-5f);
    float g = gamma[l * 32 + c], b = beta[l * 32 + c];
    float val = (g_zpre[i] - mu) * rs * g + b;
    g_hl[l][i] = __float2half(fmaxf(val, 0.f));
}

// ---------------------------------------------------------------------------
// final: new_x = cat(h0..h3) @ lin_W + lin_b; masked write-back (int32 masks)
// ---------------------------------------------------------------------------
__global__ void __launch_bounds__(128) k_final(
    const float* __restrict__ x, const float* __restrict__ linW,
    const float* __restrict__ linb,
    const int* __restrict__ nmask, const int* __restrict__ emask,
    const int* __restrict__ ondp, const int* __restrict__ oedp,
    float* __restrict__ out)
{
    __shared__ float sW[128 * 8];
    __shared__ float sb[8];
    int tid = threadIdx.x;
    for (int i = tid; i < 1024; i += 128) sW[i] = linW[i];
    if (tid < 8) sb[tid] = linb[tid];
    __syncthreads();

    int n = blockIdx.x * 128 + tid;
    if (n >= NN) return;

    float acc[8];
#pragma unroll
    for (int j = 0; j < 8; j++) acc[j] = sb[j];
#pragma unroll
    for (int l = 0; l < 4; l++) {
        const uint4* cp4 = (const uint4*)(&g_hl[l][(size_t)n * 32]);
#pragma unroll
        for (int q = 0; q < 4; q++) {           // 8 channels per uint4
            uint4 r = cp4[q];
            const __half2* h2 = (const __half2*)&r;
#pragma unroll
            for (int p = 0; p < 4; p++) {
                float2 f = __half22float2(h2[p]);
                float c0 = f.x, c1 = f.y;
                int kk = l * 32 + q * 8 + 2 * p;
                const float4* w0 = (const float4*)&sW[kk * 8];
                const float4* w1 = (const float4*)&sW[(kk + 1) * 8];
                float4 a0 = w0[0], b0 = w0[1], a1 = w1[0], b1 = w1[1];
                acc[0] = fmaf(c0, a0.x, acc[0]); acc[0] = fmaf(c1, a1.x, acc[0]);
                acc[1] = fmaf(c0, a0.y, acc[1]); acc[1] = fmaf(c1, a1.y, acc[1]);
                acc[2] = fmaf(c0, a0.z, acc[2]); acc[2] = fmaf(c1, a1.z, acc[2]);
                acc[3] = fmaf(c0, a0.w, acc[3]); acc[3] = fmaf(c1, a1.w, acc[3]);
                acc[4] = fmaf(c0, b0.x, acc[4]); acc[4] = fmaf(c1, b1.x, acc[4]);
                acc[5] = fmaf(c0, b0.y, acc[5]); acc[5] = fmaf(c1, b1.y, acc[5]);
                acc[6] = fmaf(c0, b0.z, acc[6]); acc[6] = fmaf(c1, b1.z, acc[6]);
                acc[7] = fmaf(c0, b0.w, acc[7]); acc[7] = fmaf(c1, b1.w, acc[7]);
            }
        }
    }

    int ond = ondp[0], oed = oedp[0];
    bool nm = nmask[n] != 0;
    bool em = emask[n] != 0;
#pragma unroll
    for (int j = 0; j < 8; j++) {
        bool take = (j >= 1) && ((nm && j < ond + 1) || (em && j < oed + 1));
        out[(size_t)n * 8 + j] = take ? acc[j] : x[(size_t)n * 8 + j];
    }
}

// ---------------------------------------------------------------------------
extern "C" void kernel_launch(void* const* d_in, const int* in_sizes, int n_in,
                              void* d_out, int out_size) {
    const float* x     = (const float*)d_in[0];
    const float* t     = (const float*)d_in[1];
    const int*   ei    = (const int*)d_in[2];
    const int*   nmask = (const int*)d_in[3];
    const int*   emask = (const int*)d_in[4];
    const int*   ondp  = (const int*)d_in[5];
    const int*   oedp  = (const int*)d_in[6];
    const float* W1f   = (const float*)d_in[7];
    const float* b1f   = (const float*)d_in[8];
    const float* W2f   = (const float*)d_in[9];
    const float* b2f   = (const float*)d_in[10];
    const float* W1r   = (const float*)d_in[11];
    const float* b1r   = (const float*)d_in[12];
    const float* W2r   = (const float*)d_in[13];
    const float* b2r   = (const float*)d_in[14];
    const float* eps   = (const float*)d_in[15];
    const float* gam   = (const float*)d_in[16];
    const float* bet   = (const float*)d_in[17];
    const float* linW  = (const float*)d_in[18];
    const float* linb  = (const float*)d_in[19];
    float* out = (float*)d_out;

    const int* src = ei;
    const int* dst = ei + NE;

    // init + CSR build (once per launch)
    k_init<<<(NN * 16) / 256, 256>>>(x, t);
    k_count<<<NE / 256, 256>>>(dst);
    k_scan1<<<256, 1024>>>();
    k_scan2<<<1, 256>>>();
    k_scan3<<<NN / 256, 256>>>();
    k_fill<<<NE / 256, 256>>>(src, dst);

    __half* h0p;  cudaGetSymbolAddress((void**)&h0p, g_h0);
    __half* hlp;  cudaGetSymbolAddress((void**)&hlp, g_hl);

    // layer 0 (padded K=12, h0 stride 16 halfs = 32B rows; 2 chunk-threads/node)
    k_gatherH<1, 16><<<(NN * 2) / 256, 256>>>(h0p);
    k_node<12, 9, 16><<<NN / 128, 128>>>(h0p, W1f, b1f, W2f, b2f, eps, 0);
    k_stats<<<1024, 256>>>(0);
    k_bn<<<(NN * 32) / 256, 256>>>(gam, bet, 0);

    // layers 1..3 (64B half rows; 4 chunk-threads per node)
    for (int l = 1; l < 4; l++) {
        const __half* hprev = hlp + (size_t)(l - 1) * NN * 32;
        k_gatherH<2, 32><<<(NN * 4) / 256, 256>>>(hprev);
        k_node<32, 32, 32><<<NN / 128, 128>>>(hprev,
                                              W1r + (l - 1) * 1024, b1r + (l - 1) * 32,
                                              W2r + (l - 1) * 1024, b2r + (l - 1) * 32,
                                              eps, l);
        k_stats<<<1024, 256>>>(l);
        k_bn<<<(NN * 32) / 256, 256>>>(gam, bet, l);
    }

    k_final<<<NN / 128, 128>>>(x, linW, linb, nmask, emask, ondp, oedp, out);
}

// round 13
// speedup vs baseline: 1.5472x; 1.0172x over previous
#include <cuda_runtime.h>
#include <cuda_fp16.h>
#include <stdint.h>

#define NN 262144
#define NE (4*1024*1024)

typedef unsigned long long ull;

// Scratch (device globals — no allocation allowed; zero-initialized at load)
__device__ __half g_h0[NN * 16];                // layer-0 input, half, padded 9->16 (32B rows)
__device__ __half g_hl[4][NN * 32];             // DENSE per-layer outputs, half (64B rows)
__device__ float  g_agg[NN * 32];               // gather output, fp32
__device__ float  g_zpre[NN * 32];              // pre-BN MLP output, fp32
__device__ float  g_stats[256];                 // per layer: [l*64+c]=sum, [l*64+32+c]=sumsq
// CSR-by-dst scratch
__device__ int g_deg[NN];                       // invariant: ZERO at kernel_launch entry
__device__ int g_off[NN + 1];
__device__ int g_pos[NN];
__device__ int g_csr[NE];
__device__ int g_bsum[256];
__device__ int g_bsum2[256];
__device__ unsigned int g_ticket;               // scan1 last-block ticket (reset in scan1)

// packed f32x2 helpers (FFMA2 is PTX-only on sm_103a; ptxas never auto-fuses)
__device__ __forceinline__ ull pk2(float a, float b) {
    ull r; asm("mov.b64 %0,{%1,%2};" : "=l"(r) : "f"(a), "f"(b)); return r;
}
__device__ __forceinline__ void upk2(ull v, float& a, float& b) {
    asm("mov.b64 {%0,%1},%2;" : "=f"(a), "=f"(b) : "l"(v));
}
__device__ __forceinline__ ull fma2(ull a, ull b, ull c) {
    ull d; asm("fma.rn.f32x2 %0,%1,%2,%3;" : "=l"(d) : "l"(a), "l"(b), "l"(c)); return d;
}

// accumulate 8 halfs (one uint4) into 8 float accumulators
__device__ __forceinline__ void acc8(float* a, uint4 v) {
    const __half2* h = (const __half2*)&v;
#pragma unroll
    for (int q = 0; q < 4; q++) {
        float2 f = __half22float2(h[q]);
        a[2 * q + 0] += f.x;
        a[2 * q + 1] += f.y;
    }
}

// ---------------------------------------------------------------------------
// init+count fused: build h0, zero stats, AND count degrees (deg==0 on entry:
// zero-init on first call, re-zeroed by k_scan3 on every call)
// ---------------------------------------------------------------------------
__global__ void k_initcount(const float* __restrict__ x, const float* __restrict__ t,
                            const int* __restrict__ dst) {
    int i = blockIdx.x * blockDim.x + threadIdx.x;
    if (i < NN * 16) {
        int n = i >> 4, k = i & 15;
        float v = 0.f;
        if (k < 8) v = x[n * 8 + k];
        else if (k == 8) v = t[0];
        g_h0[i] = __float2half(v);
    }
    if (i < 256) g_stats[i] = 0.f;
    if (i < NE) atomicAdd(&g_deg[dst[i]], 1);
}

// ---------------------------------------------------------------------------
// scan1 with fused block-sum scan (last-block ticket)
// ---------------------------------------------------------------------------
__global__ void k_scan1() {   // 256 blocks x 1024 threads
    __shared__ int s[1024];
    int tid = threadIdx.x;
    int i = blockIdx.x * 1024 + tid;
    int v = g_deg[i];
    s[tid] = v;
    __syncthreads();
#pragma unroll
    for (int off = 1; off < 1024; off <<= 1) {
        int tv = (tid >= off) ? s[tid - off] : 0;
        __syncthreads();
        s[tid] += tv;
        __syncthreads();
    }
    g_off[i] = s[tid] - v;                 // exclusive within block
    if (tid == 1023) g_bsum[blockIdx.x] = s[1023];

    // last arriving block scans the 256 block sums (deterministic result)
    __shared__ unsigned int isLast;
    __threadfence();
    __syncthreads();
    if (tid == 0) {
        unsigned int old = atomicAdd(&g_ticket, 1u);
        isLast = (old == 255u) ? 1u : 0u;
        if (isLast) g_ticket = 0u;         // reset for next launch
    }
    __syncthreads();
    if (isLast) {
        __shared__ int bs[256];
        if (tid < 256) bs[tid] = g_bsum[tid];
        __syncthreads();
#pragma unroll
        for (int off = 1; off < 256; off <<= 1) {
            int tv = (tid < 256 && tid >= off) ? bs[tid - off] : 0;
            __syncthreads();
            if (tid < 256) bs[tid] += tv;
            __syncthreads();
        }
        if (tid < 256) g_bsum2[tid] = bs[tid] - g_bsum[tid];  // exclusive
    }
}

__global__ void k_scan3() {
    int i = blockIdx.x * blockDim.x + threadIdx.x;
    if (i < NN) {
        int o = g_off[i] + g_bsum2[i >> 10];
        g_off[i] = o;
        g_pos[i] = o;
        g_deg[i] = 0;                      // restore entry invariant for next call
    }
    if (i == 0) g_off[NN] = NE;
}

__global__ void k_fill(const int* __restrict__ src, const int* __restrict__ dst) {
    int e = blockIdx.x * blockDim.x + threadIdx.x;
    if (e >= NE) return;
    int slot = atomicAdd(&g_pos[dst[e]], 1);
    g_csr[slot] = src[e];
}

// ---------------------------------------------------------------------------
// gather (half source): chunk-per-thread, each chunk = 8 channels (one uint4)
// ---------------------------------------------------------------------------
template<int SHIFT, int ROWH>
__global__ void __launch_bounds__(256) k_gatherH(const __half* __restrict__ hbase) {
    int idx = blockIdx.x * blockDim.x + threadIdx.x;
    int n = idx >> SHIFT;
    int c = idx & ((1 << SHIFT) - 1);
    if (n >= NN) return;
    int k = g_off[n], end = g_off[n + 1];
    float a[8];
#pragma unroll
    for (int q = 0; q < 8; q++) a[q] = 0.f;
    for (; k + 4 <= end; k += 4) {
        int s0 = g_csr[k], s1 = g_csr[k + 1], s2 = g_csr[k + 2], s3 = g_csr[k + 3];
        uint4 v0 = *((const uint4*)(hbase + (size_t)s0 * ROWH) + c);
        uint4 v1 = *((const uint4*)(hbase + (size_t)s1 * ROWH) + c);
        uint4 v2 = *((const uint4*)(hbase + (size_t)s2 * ROWH) + c);
        uint4 v3 = *((const uint4*)(hbase + (size_t)s3 * ROWH) + c);
        acc8(a, v0); acc8(a, v1); acc8(a, v2); acc8(a, v3);
    }
    for (; k < end; k++) {
        int s0 = g_csr[k];
        uint4 v0 = *((const uint4*)(hbase + (size_t)s0 * ROWH) + c);
        acc8(a, v0);
    }
    float* ap = g_agg + (size_t)n * 32 + c * 8;
    float4 o0; o0.x = a[0]; o0.y = a[1]; o0.z = a[2]; o0.w = a[3];
    float4 o1; o1.x = a[4]; o1.y = a[5]; o1.z = a[6]; o1.w = a[7];
    *(float4*)(ap + 0) = o0;
    *(float4*)(ap + 4) = o1;
}

// ---------------------------------------------------------------------------
// node MLP (packed f32x2 GEMMs): z=(1+eps)h+agg; u=relu(z@W1+b1);
// v=u@W2+b2 -> g_zpre
// ---------------------------------------------------------------------------
template<int K, int KROWS, int HSTH>
__global__ void __launch_bounds__(128) k_node(
    const __half* __restrict__ hprev,
    const float* __restrict__ W1, const float* __restrict__ b1,
    const float* __restrict__ W2, const float* __restrict__ b2,
    const float* __restrict__ eps, int l)
{
    __shared__ __align__(16) float sW1[K * 32];
    __shared__ __align__(16) float sW2[32 * 32];
    __shared__ __align__(16) float sb1[32];
    __shared__ __align__(16) float sb2[32];
    int tid = threadIdx.x;
    for (int i = tid; i < K * 32; i += 128) {
        int k = i >> 5;
        sW1[i] = (k < KROWS) ? W1[i] : 0.f;
    }
    for (int i = tid; i < 1024; i += 128) sW2[i] = W2[i];
    if (tid < 32) { sb1[tid] = b1[tid]; sb2[tid] = b2[tid]; }
    __syncthreads();

    int n = blockIdx.x * 128 + tid;
    if (n >= NN) return;
    float e1 = 1.f + eps[l];
    const uint4* hp4 = (const uint4*)(hprev + (size_t)n * HSTH);
    const float* ap = g_agg + (size_t)n * 32;

    float hf[HSTH];
#pragma unroll
    for (int q = 0; q < HSTH / 8; q++) {
        uint4 r = hp4[q];
        const __half2* h2 = (const __half2*)&r;
#pragma unroll
        for (int p = 0; p < 4; p++) {
            float2 f = __half22float2(h2[p]);
            hf[q * 8 + 2 * p + 0] = f.x;
            hf[q * 8 + 2 * p + 1] = f.y;
        }
    }

    float z[K];
#pragma unroll
    for (int k = 0; k < K; k += 4) {
        float4 a4 = *(const float4*)(ap + k);
        z[k + 0] = fmaf(e1, hf[k + 0], a4.x);
        z[k + 1] = fmaf(e1, hf[k + 1], a4.y);
        z[k + 2] = fmaf(e1, hf[k + 2], a4.z);
        z[k + 3] = fmaf(e1, hf[k + 3], a4.w);
    }

    ull u2[16];
    const ull* b1p = (const ull*)sb1;
#pragma unroll
    for (int jj = 0; jj < 16; jj++) u2[jj] = b1p[jj];
#pragma unroll
    for (int k = 0; k < K; k++) {
        ull zz = pk2(z[k], z[k]);
        const ulonglong2* w = (const ulonglong2*)&sW1[k << 5];
#pragma unroll
        for (int jj = 0; jj < 8; jj++) {
            ulonglong2 wv = w[jj];
            u2[2 * jj + 0] = fma2(zz, wv.x, u2[2 * jj + 0]);
            u2[2 * jj + 1] = fma2(zz, wv.y, u2[2 * jj + 1]);
        }
    }
    float u[32];
#pragma unroll
    for (int jj = 0; jj < 16; jj++) upk2(u2[jj], u[2 * jj], u[2 * jj + 1]);
#pragma unroll
    for (int j = 0; j < 32; j++) u[j] = fmaxf(u[j], 0.f);

    ull v2[16];
    const ull* b2p = (const ull*)sb2;
#pragma unroll
    for (int jj = 0; jj < 16; jj++) v2[jj] = b2p[jj];
#pragma unroll
    for (int k = 0; k < 32; k++) {
        ull uu = pk2(u[k], u[k]);
        const ulonglong2* w = (const ulonglong2*)&sW2[k << 5];
#pragma unroll
        for (int jj = 0; jj < 8; jj++) {
            ulonglong2 wv = w[jj];
            v2[2 * jj + 0] = fma2(uu, wv.x, v2[2 * jj + 0]);
            v2[2 * jj + 1] = fma2(uu, wv.y, v2[2 * jj + 1]);
        }
    }

    ulonglong2* zp = (ulonglong2*)(g_zpre + (size_t)n * 32);
#pragma unroll
    for (int q = 0; q < 8; q++) {
        ulonglong2 o; o.x = v2[2 * q]; o.y = v2[2 * q + 1];
        zp[q] = o;
    }
}

// ---------------------------------------------------------------------------
// BN stats: lane c owns channel c (coalesced); 512 blocks (smaller atomic tail)
// ---------------------------------------------------------------------------
__global__ void k_stats(int l) {
    int lane = threadIdx.x & 31;
    int warpId = (blockIdx.x * blockDim.x + threadIdx.x) >> 5;
    int nwarps = (gridDim.x * blockDim.x) >> 5;
    float s = 0.f, q = 0.f;
    for (int n = warpId; n < NN; n += nwarps) {
        float v = g_zpre[(size_t)n * 32 + lane];
        s += v;
        q += v * v;
    }
    __shared__ float ss[32], sq[32];
    if (threadIdx.x < 32) { ss[threadIdx.x] = 0.f; sq[threadIdx.x] = 0.f; }
    __syncthreads();
    atomicAdd(&ss[lane], s);
    atomicAdd(&sq[lane], q);
    __syncthreads();
    if (threadIdx.x < 32) {
        atomicAdd(&g_stats[l * 64 + threadIdx.x], ss[threadIdx.x]);
        atomicAdd(&g_stats[l * 64 + 32 + threadIdx.x], sq[threadIdx.x]);
    }
}

// ---------------------------------------------------------------------------
// BN + ReLU -> dense half layer buffer
// ---------------------------------------------------------------------------
__global__ void k_bn(const float* __restrict__ gamma, const float* __restrict__ beta, int l) {
    int i = blockIdx.x * blockDim.x + threadIdx.x;
    if (i >= NN * 32) return;
    int c = i & 31;
    const float inv = 1.0f / (float)NN;
    float mu = g_stats[l * 64 + c] * inv;
    float var = g_stats[l * 64 + 32 + c] * inv - mu * mu;
    float rs = rsqrtf(var + 1e-5f);
    float g = gamma[l * 32 + c], b = beta[l * 32 + c];
    float val = (g_zpre[i] - mu) * rs * g + b;
    g_hl[l][i] = __float2half(fmaxf(val, 0.f));
}

// ---------------------------------------------------------------------------
// final: new_x = cat(h0..h3) @ lin_W + lin_b; masked write-back (int32 masks)
// ---------------------------------------------------------------------------
__global__ void __launch_bounds__(128) k_final(
    const float* __restrict__ x, const float* __restrict__ linW,
    const float* __restrict__ linb,
    const int* __restrict__ nmask, const int* __restrict__ emask,
    const int* __restrict__ ondp, const int* __restrict__ oedp,
    float* __restrict__ out)
{
    __shared__ float sW[128 * 8];
    __shared__ float sb[8];
    int tid = threadIdx.x;
    for (int i = tid; i < 1024; i += 128) sW[i] = linW[i];
    if (tid < 8) sb[tid] = linb[tid];
    __syncthreads();

    int n = blockIdx.x * 128 + tid;
    if (n >= NN) return;

    float acc[8];
#pragma unroll
    for (int j = 0; j < 8; j++) acc[j] = sb[j];
#pragma unroll
    for (int l = 0; l < 4; l++) {
        const uint4* cp4 = (const uint4*)(&g_hl[l][(size_t)n * 32]);
#pragma unroll
        for (int q = 0; q < 4; q++) {           // 8 channels per uint4
            uint4 r = cp4[q];
            const __half2* h2 = (const __half2*)&r;
#pragma unroll
            for (int p = 0; p < 4; p++) {
                float2 f = __half22float2(h2[p]);
                float c0 = f.x, c1 = f.y;
                int kk = l * 32 + q * 8 + 2 * p;
                const float4* w0 = (const float4*)&sW[kk * 8];
                const float4* w1 = (const float4*)&sW[(kk + 1) * 8];
                float4 a0 = w0[0], b0 = w0[1], a1 = w1[0], b1 = w1[1];
                acc[0] = fmaf(c0, a0.x, acc[0]); acc[0] = fmaf(c1, a1.x, acc[0]);
                acc[1] = fmaf(c0, a0.y, acc[1]); acc[1] = fmaf(c1, a1.y, acc[1]);
                acc[2] = fmaf(c0, a0.z, acc[2]); acc[2] = fmaf(c1, a1.z, acc[2]);
                acc[3] = fmaf(c0, a0.w, acc[3]); acc[3] = fmaf(c1, a1.w, acc[3]);
                acc[4] = fmaf(c0, b0.x, acc[4]); acc[4] = fmaf(c1, b1.x, acc[4]);
                acc[5] = fmaf(c0, b0.y, acc[5]); acc[5] = fmaf(c1, b1.y, acc[5]);
                acc[6] = fmaf(c0, b0.z, acc[6]); acc[6] = fmaf(c1, b1.z, acc[6]);
                acc[7] = fmaf(c0, b0.w, acc[7]); acc[7] = fmaf(c1, b1.w, acc[7]);
            }
        }
    }

    int ond = ondp[0], oed = oedp[0];
    bool nm = nmask[n] != 0;
    bool em = emask[n] != 0;
#pragma unroll
    for (int j = 0; j < 8; j++) {
        bool take = (j >= 1) && ((nm && j < ond + 1) || (em && j < oed + 1));
        out[(size_t)n * 8 + j] = take ? acc[j] : x[(size_t)n * 8 + j];
    }
}

// ---------------------------------------------------------------------------
extern "C" void kernel_launch(void* const* d_in, const int* in_sizes, int n_in,
                              void* d_out, int out_size) {
    const float* x     = (const float*)d_in[0];
    const float* t     = (const float*)d_in[1];
    const int*   ei    = (const int*)d_in[2];
    const int*   nmask = (const int*)d_in[3];
    const int*   emask = (const int*)d_in[4];
    const int*   ondp  = (const int*)d_in[5];
    const int*   oedp  = (const int*)d_in[6];
    const float* W1f   = (const float*)d_in[7];
    const float* b1f   = (const float*)d_in[8];
    const float* W2f   = (const float*)d_in[9];
    const float* b2f   = (const float*)d_in[10];
    const float* W1r   = (const float*)d_in[11];
    const float* b1r   = (const float*)d_in[12];
    const float* W2r   = (const float*)d_in[13];
    const float* b2r   = (const float*)d_in[14];
    const float* eps   = (const float*)d_in[15];
    const float* gam   = (const float*)d_in[16];
    const float* bet   = (const float*)d_in[17];
    const float* linW  = (const float*)d_in[18];
    const float* linb  = (const float*)d_in[19];
    float* out = (float*)d_out;

    const int* src = ei;
    const int* dst = ei + NE;

    // fused init+count, then scan(+fused block-sum scan), scan3(+deg reset), fill
    k_initcount<<<NE / 256, 256>>>(x, t, dst);
    k_scan1<<<256, 1024>>>();
    k_scan3<<<NN / 256, 256>>>();
    k_fill<<<NE / 256, 256>>>(src, dst);

    __half* h0p;  cudaGetSymbolAddress((void**)&h0p, g_h0);
    __half* hlp;  cudaGetSymbolAddress((void**)&hlp, g_hl);

    // layer 0 (padded K=12, h0 stride 16 halfs = 32B rows; 2 chunk-threads/node)
    k_gatherH<1, 16><<<(NN * 2) / 256, 256>>>(h0p);
    k_node<12, 9, 16><<<NN / 128, 128>>>(h0p, W1f, b1f, W2f, b2f, eps, 0);
    k_stats<<<512, 256>>>(0);
    k_bn<<<(NN * 32) / 256, 256>>>(gam, bet, 0);

    // layers 1..3 (64B half rows; 4 chunk-threads per node)
    for (int l = 1; l < 4; l++) {
        const __half* hprev = hlp + (size_t)(l - 1) * NN * 32;
        k_gatherH<2, 32><<<(NN * 4) / 256, 256>>>(hprev);
        k_node<32, 32, 32><<<NN / 128, 128>>>(hprev,
                                              W1r + (l - 1) * 1024, b1r + (l - 1) * 32,
                                              W2r + (l - 1) * 1024, b2r + (l - 1) * 32,
                                              eps, l);
        k_stats<<<512, 256>>>(l);
        k_bn<<<(NN * 32) / 256, 256>>>(gam, bet, l);
    }

    k_final<<<NN / 128, 128>>>(x, linW, linb, nmask, emask, ondp, oedp, out);
}

// round 14
// speedup vs baseline: 1.6778x; 1.0844x over previous
#include <cuda_runtime.h>
#include <cuda_fp16.h>
#include <stdint.h>

#define NN 262144
#define NE (4*1024*1024)

typedef unsigned long long ull;

// Scratch (device globals — no allocation allowed; zero-initialized at load)
__device__ __half g_h0[NN * 16];                // layer-0 input, half, padded 9->16 (32B rows)
__device__ __half g_hl[4][NN * 32];             // DENSE per-layer outputs, half (64B rows)
__device__ float  g_agg[NN * 32];               // gather output, fp32
__device__ float  g_zpre[NN * 32];              // pre-BN MLP output, fp32
__device__ float  g_stats[256];                 // per layer: [l*64+c]=sum, [l*64+32+c]=sumsq
// CSR-by-dst scratch
__device__ int g_deg[NN];                       // invariant: ZERO at kernel_launch entry
__device__ int g_off[NN + 1];
__device__ int g_pos[NN];
__device__ int g_csr[NE];
__device__ int g_bsum[256];
__device__ int g_bsum2[256];
__device__ unsigned int g_ticket;               // scan1 last-block ticket (reset in scan1)

// packed f32x2 helpers (FFMA2 is PTX-only on sm_103a; ptxas never auto-fuses)
__device__ __forceinline__ ull pk2(float a, float b) {
    ull r; asm("mov.b64 %0,{%1,%2};" : "=l"(r) : "f"(a), "f"(b)); return r;
}
__device__ __forceinline__ void upk2(ull v, float& a, float& b) {
    asm("mov.b64 {%0,%1},%2;" : "=f"(a), "=f"(b) : "l"(v));
}
__device__ __forceinline__ ull fma2(ull a, ull b, ull c) {
    ull d; asm("fma.rn.f32x2 %0,%1,%2,%3;" : "=l"(d) : "l"(a), "l"(b), "l"(c)); return d;
}

// accumulate 8 halfs (one uint4) into 8 float accumulators
__device__ __forceinline__ void acc8(float* a, uint4 v) {
    const __half2* h = (const __half2*)&v;
#pragma unroll
    for (int q = 0; q < 4; q++) {
        float2 f = __half22float2(h[q]);
        a[2 * q + 0] += f.x;
        a[2 * q + 1] += f.y;
    }
}

// ---------------------------------------------------------------------------
// init+count fused: build h0, zero stats, AND count degrees (deg==0 on entry)
// ---------------------------------------------------------------------------
__global__ void k_initcount(const float* __restrict__ x, const float* __restrict__ t,
                            const int* __restrict__ dst) {
    int i = blockIdx.x * blockDim.x + threadIdx.x;
    if (i < NN * 16) {
        int n = i >> 4, k = i & 15;
        float v = 0.f;
        if (k < 8) v = x[n * 8 + k];
        else if (k == 8) v = t[0];
        g_h0[i] = __float2half(v);
    }
    if (i < 256) g_stats[i] = 0.f;
    if (i < NE) atomicAdd(&g_deg[dst[i]], 1);
}

// ---------------------------------------------------------------------------
// scan1 with fused block-sum scan (last-block ticket)
// ---------------------------------------------------------------------------
__global__ void k_scan1() {   // 256 blocks x 1024 threads
    __shared__ int s[1024];
    int tid = threadIdx.x;
    int i = blockIdx.x * 1024 + tid;
    int v = g_deg[i];
    s[tid] = v;
    __syncthreads();
#pragma unroll
    for (int off = 1; off < 1024; off <<= 1) {
        int tv = (tid >= off) ? s[tid - off] : 0;
        __syncthreads();
        s[tid] += tv;
        __syncthreads();
    }
    g_off[i] = s[tid] - v;                 // exclusive within block
    if (tid == 1023) g_bsum[blockIdx.x] = s[1023];

    __shared__ unsigned int isLast;
    __threadfence();
    __syncthreads();
    if (tid == 0) {
        unsigned int old = atomicAdd(&g_ticket, 1u);
        isLast = (old == 255u) ? 1u : 0u;
        if (isLast) g_ticket = 0u;
    }
    __syncthreads();
    if (isLast) {
        __shared__ int bs[256];
        if (tid < 256) bs[tid] = g_bsum[tid];
        __syncthreads();
#pragma unroll
        for (int off = 1; off < 256; off <<= 1) {
            int tv = (tid < 256 && tid >= off) ? bs[tid - off] : 0;
            __syncthreads();
            if (tid < 256) bs[tid] += tv;
            __syncthreads();
        }
        if (tid < 256) g_bsum2[tid] = bs[tid] - g_bsum[tid];
    }
}

__global__ void k_scan3() {
    int i = blockIdx.x * blockDim.x + threadIdx.x;
    if (i < NN) {
        int o = g_off[i] + g_bsum2[i >> 10];
        g_off[i] = o;
        g_pos[i] = o;
        g_deg[i] = 0;                      // restore entry invariant
    }
    if (i == 0) g_off[NN] = NE;
}

__global__ void k_fill(const int* __restrict__ src, const int* __restrict__ dst) {
    int e = blockIdx.x * blockDim.x + threadIdx.x;
    if (e >= NE) return;
    int slot = atomicAdd(&g_pos[dst[e]], 1);
    g_csr[slot] = src[e];
}

// ---------------------------------------------------------------------------
// gather (half source): chunk-per-thread, each chunk = 8 channels (one uint4)
// ---------------------------------------------------------------------------
template<int SHIFT, int ROWH>
__global__ void __launch_bounds__(256) k_gatherH(const __half* __restrict__ hbase) {
    int idx = blockIdx.x * blockDim.x + threadIdx.x;
    int n = idx >> SHIFT;
    int c = idx & ((1 << SHIFT) - 1);
    if (n >= NN) return;
    int k = g_off[n], end = g_off[n + 1];
    float a[8];
#pragma unroll
    for (int q = 0; q < 8; q++) a[q] = 0.f;
    for (; k + 4 <= end; k += 4) {
        int s0 = g_csr[k], s1 = g_csr[k + 1], s2 = g_csr[k + 2], s3 = g_csr[k + 3];
        uint4 v0 = *((const uint4*)(hbase + (size_t)s0 * ROWH) + c);
        uint4 v1 = *((const uint4*)(hbase + (size_t)s1 * ROWH) + c);
        uint4 v2 = *((const uint4*)(hbase + (size_t)s2 * ROWH) + c);
        uint4 v3 = *((const uint4*)(hbase + (size_t)s3 * ROWH) + c);
        acc8(a, v0); acc8(a, v1); acc8(a, v2); acc8(a, v3);
    }
    for (; k < end; k++) {
        int s0 = g_csr[k];
        uint4 v0 = *((const uint4*)(hbase + (size_t)s0 * ROWH) + c);
        acc8(a, v0);
    }
    float* ap = g_agg + (size_t)n * 32 + c * 8;
    float4 o0; o0.x = a[0]; o0.y = a[1]; o0.z = a[2]; o0.w = a[3];
    float4 o1; o1.x = a[4]; o1.y = a[5]; o1.z = a[6]; o1.w = a[7];
    *(float4*)(ap + 0) = o0;
    *(float4*)(ap + 4) = o1;
}

// ---------------------------------------------------------------------------
// node MLP (packed f32x2 GEMMs) + FUSED BN-stats:
// z=(1+eps)h+agg; u=relu(z@W1+b1); v=u@W2+b2 -> g_zpre;
// per-warp shfl-butterfly per channel (constant indices), smem across warps,
// one global atomicAdd per channel per block -> g_stats[l*64 + ...]
// ---------------------------------------------------------------------------
template<int K, int KROWS, int HSTH>
__global__ void __launch_bounds__(128) k_node(
    const __half* __restrict__ hprev,
    const float* __restrict__ W1, const float* __restrict__ b1,
    const float* __restrict__ W2, const float* __restrict__ b2,
    const float* __restrict__ eps, int l)
{
    __shared__ __align__(16) float sW1[K * 32];
    __shared__ __align__(16) float sW2[32 * 32];
    __shared__ __align__(16) float sb1[32];
    __shared__ __align__(16) float sb2[32];
    __shared__ float ss2[32], sq2[32];
    int tid = threadIdx.x;
    for (int i = tid; i < K * 32; i += 128) {
        int k = i >> 5;
        sW1[i] = (k < KROWS) ? W1[i] : 0.f;
    }
    for (int i = tid; i < 1024; i += 128) sW2[i] = W2[i];
    if (tid < 32) { sb1[tid] = b1[tid]; sb2[tid] = b2[tid]; ss2[tid] = 0.f; sq2[tid] = 0.f; }
    __syncthreads();

    int n = blockIdx.x * 128 + tid;     // grid exactly covers NN
    float e1 = 1.f + eps[l];
    const uint4* hp4 = (const uint4*)(hprev + (size_t)n * HSTH);
    const float* ap = g_agg + (size_t)n * 32;

    float hf[HSTH];
#pragma unroll
    for (int q = 0; q < HSTH / 8; q++) {
        uint4 r = hp4[q];
        const __half2* h2 = (const __half2*)&r;
#pragma unroll
        for (int p = 0; p < 4; p++) {
            float2 f = __half22float2(h2[p]);
            hf[q * 8 + 2 * p + 0] = f.x;
            hf[q * 8 + 2 * p + 1] = f.y;
        }
    }

    float z[K];
#pragma unroll
    for (int k = 0; k < K; k += 4) {
        float4 a4 = *(const float4*)(ap + k);
        z[k + 0] = fmaf(e1, hf[k + 0], a4.x);
        z[k + 1] = fmaf(e1, hf[k + 1], a4.y);
        z[k + 2] = fmaf(e1, hf[k + 2], a4.z);
        z[k + 3] = fmaf(e1, hf[k + 3], a4.w);
    }

    ull u2[16];
    const ull* b1p = (const ull*)sb1;
#pragma unroll
    for (int jj = 0; jj < 16; jj++) u2[jj] = b1p[jj];
#pragma unroll
    for (int k = 0; k < K; k++) {
        ull zz = pk2(z[k], z[k]);
        const ulonglong2* w = (const ulonglong2*)&sW1[k << 5];
#pragma unroll
        for (int jj = 0; jj < 8; jj++) {
            ulonglong2 wv = w[jj];
            u2[2 * jj + 0] = fma2(zz, wv.x, u2[2 * jj + 0]);
            u2[2 * jj + 1] = fma2(zz, wv.y, u2[2 * jj + 1]);
        }
    }
    float u[32];
#pragma unroll
    for (int jj = 0; jj < 16; jj++) upk2(u2[jj], u[2 * jj], u[2 * jj + 1]);
#pragma unroll
    for (int j = 0; j < 32; j++) u[j] = fmaxf(u[j], 0.f);

    ull v2[16];
    const ull* b2p = (const ull*)sb2;
#pragma unroll
    for (int jj = 0; jj < 16; jj++) v2[jj] = b2p[jj];
#pragma unroll
    for (int k = 0; k < 32; k++) {
        ull uu = pk2(u[k], u[k]);
        const ulonglong2* w = (const ulonglong2*)&sW2[k << 5];
#pragma unroll
        for (int jj = 0; jj < 8; jj++) {
            ulonglong2 wv = w[jj];
            v2[2 * jj + 0] = fma2(uu, wv.x, v2[2 * jj + 0]);
            v2[2 * jj + 1] = fma2(uu, wv.y, v2[2 * jj + 1]);
        }
    }

    ulonglong2* zp = (ulonglong2*)(g_zpre + (size_t)n * 32);
#pragma unroll
    for (int q = 0; q < 8; q++) {
        ulonglong2 o; o.x = v2[2 * q]; o.y = v2[2 * q + 1];
        zp[q] = o;
    }

    // fused BN stats: unpack, butterfly-reduce each channel across the warp
    float vv[32];
#pragma unroll
    for (int jj = 0; jj < 16; jj++) upk2(v2[jj], vv[2 * jj], vv[2 * jj + 1]);

    int lane = tid & 31;
    float mysum = 0.f, mysq = 0.f;
#pragma unroll
    for (int c = 0; c < 32; c++) {
        float s = vv[c];
        float q = s * s;
#pragma unroll
        for (int off = 16; off > 0; off >>= 1) {
            s += __shfl_xor_sync(0xFFFFFFFFu, s, off);
            q += __shfl_xor_sync(0xFFFFFFFFu, q, off);
        }
        if (lane == c) { mysum = s; mysq = q; }
    }
    atomicAdd(&ss2[lane], mysum);
    atomicAdd(&sq2[lane], mysq);
    __syncthreads();
    if (tid < 32) {
        atomicAdd(&g_stats[l * 64 + tid], ss2[tid]);
        atomicAdd(&g_stats[l * 64 + 32 + tid], sq2[tid]);
    }
}

// ---------------------------------------------------------------------------
// BN + ReLU -> dense half layer buffer (layers 0..2), 4 channels/thread
// ---------------------------------------------------------------------------
__global__ void k_bn(const float* __restrict__ gamma, const float* __restrict__ beta, int l) {
    int i = blockIdx.x * blockDim.x + threadIdx.x;   // NN*8 total
    if (i >= NN * 8) return;
    int c0 = (i & 7) * 4;
    const float inv = 1.0f / (float)NN;
    float4 zv = *(const float4*)(g_zpre + (size_t)i * 4);
    float o[4];
#pragma unroll
    for (int q = 0; q < 4; q++) {
        int c = c0 + q;
        float mu = g_stats[l * 64 + c] * inv;
        float var = g_stats[l * 64 + 32 + c] * inv - mu * mu;
        float rs = rsqrtf(var + 1e-5f);
        float zq = (q == 0) ? zv.x : (q == 1) ? zv.y : (q == 2) ? zv.z : zv.w;
        float val = (zq - mu) * rs * gamma[l * 32 + c] + beta[l * 32 + c];
        o[q] = fmaxf(val, 0.f);
    }
    __half2 h01 = __floats2half2_rn(o[0], o[1]);
    __half2 h23 = __floats2half2_rn(o[2], o[3]);
    uint2 ov;
    ov.x = *(const unsigned int*)&h01;
    ov.y = *(const unsigned int*)&h23;
    *(uint2*)(&g_hl[l][(size_t)i * 4]) = ov;
}

// ---------------------------------------------------------------------------
// bn(layer3) + final fused: node-per-thread. BN+ReLU on zpre row in regs,
// JK-GEMM (l=0..2 from g_hl, l=3 from regs), masked write-back.
// ---------------------------------------------------------------------------
__global__ void __launch_bounds__(128) k_bnfinal(
    const float* __restrict__ x,
    const float* __restrict__ gamma, const float* __restrict__ beta,
    const float* __restrict__ linW, const float* __restrict__ linb,
    const int* __restrict__ nmask, const int* __restrict__ emask,
    const int* __restrict__ ondp, const int* __restrict__ oedp,
    float* __restrict__ out)
{
    __shared__ float sW[128 * 8];
    __shared__ float sb[8];
    __shared__ float smu[32], srs[32], sga[32], sbe[32];
    int tid = threadIdx.x;
    for (int i = tid; i < 1024; i += 128) sW[i] = linW[i];
    if (tid < 8) sb[tid] = linb[tid];
    if (tid < 32) {
        const float inv = 1.0f / (float)NN;
        float mu = g_stats[3 * 64 + tid] * inv;
        float var = g_stats[3 * 64 + 32 + tid] * inv - mu * mu;
        smu[tid] = mu;
        srs[tid] = rsqrtf(var + 1e-5f);
        sga[tid] = gamma[3 * 32 + tid];
        sbe[tid] = beta[3 * 32 + tid];
    }
    __syncthreads();

    int n = blockIdx.x * 128 + tid;
    if (n >= NN) return;

    // BN+ReLU layer-3 row in registers
    float c3[32];
    const float4* zp = (const float4*)(g_zpre + (size_t)n * 32);
#pragma unroll
    for (int q = 0; q < 8; q++) {
        float4 zv = zp[q];
        float zq[4] = {zv.x, zv.y, zv.z, zv.w};
#pragma unroll
        for (int p = 0; p < 4; p++) {
            int c = q * 4 + p;
            float val = (zq[p] - smu[c]) * srs[c] * sga[c] + sbe[c];
            c3[c] = fmaxf(val, 0.f);
        }
    }

    float acc[8];
#pragma unroll
    for (int j = 0; j < 8; j++) acc[j] = sb[j];
    // layers 0..2 from half buffers
#pragma unroll
    for (int l = 0; l < 3; l++) {
        const uint4* cp4 = (const uint4*)(&g_hl[l][(size_t)n * 32]);
#pragma unroll
        for (int q = 0; q < 4; q++) {
            uint4 r = cp4[q];
            const __half2* h2 = (const __half2*)&r;
#pragma unroll
            for (int p = 0; p < 4; p++) {
                float2 f = __half22float2(h2[p]);
                int kk = l * 32 + q * 8 + 2 * p;
                const float4* w0 = (const float4*)&sW[kk * 8];
                const float4* w1 = (const float4*)&sW[(kk + 1) * 8];
                float4 a0 = w0[0], b0 = w0[1], a1 = w1[0], b1 = w1[1];
                float cA = f.x, cB = f.y;
                acc[0] = fmaf(cA, a0.x, acc[0]); acc[0] = fmaf(cB, a1.x, acc[0]);
                acc[1] = fmaf(cA, a0.y, acc[1]); acc[1] = fmaf(cB, a1.y, acc[1]);
                acc[2] = fmaf(cA, a0.z, acc[2]); acc[2] = fmaf(cB, a1.z, acc[2]);
                acc[3] = fmaf(cA, a0.w, acc[3]); acc[3] = fmaf(cB, a1.w, acc[3]);
                acc[4] = fmaf(cA, b0.x, acc[4]); acc[4] = fmaf(cB, b1.x, acc[4]);
                acc[5] = fmaf(cA, b0.y, acc[5]); acc[5] = fmaf(cB, b1.y, acc[5]);
                acc[6] = fmaf(cA, b0.z, acc[6]); acc[6] = fmaf(cB, b1.z, acc[6]);
                acc[7] = fmaf(cA, b0.w, acc[7]); acc[7] = fmaf(cB, b1.w, acc[7]);
            }
        }
    }
    // layer 3 from registers (fp32 — no half rounding on this segment)
#pragma unroll
    for (int k = 0; k < 32; k++) {
        const float4* w = (const float4*)&sW[(96 + k) * 8];
        float4 w0 = w[0], w1 = w[1];
        float ck = c3[k];
        acc[0] = fmaf(ck, w0.x, acc[0]);
        acc[1] = fmaf(ck, w0.y, acc[1]);
        acc[2] = fmaf(ck, w0.z, acc[2]);
        acc[3] = fmaf(ck, w0.w, acc[3]);
        acc[4] = fmaf(ck, w1.x, acc[4]);
        acc[5] = fmaf(ck, w1.y, acc[5]);
        acc[6] = fmaf(ck, w1.z, acc[6]);
        acc[7] = fmaf(ck, w1.w, acc[7]);
    }

    int ond = ondp[0], oed = oedp[0];
    bool nm = nmask[n] != 0;
    bool em = emask[n] != 0;
#pragma unroll
    for (int j = 0; j < 8; j++) {
        bool take = (j >= 1) && ((nm && j < ond + 1) || (em && j < oed + 1));
        out[(size_t)n * 8 + j] = take ? acc[j] : x[(size_t)n * 8 + j];
    }
}

// ---------------------------------------------------------------------------
extern "C" void kernel_launch(void* const* d_in, const int* in_sizes, int n_in,
                              void* d_out, int out_size) {
    const float* x     = (const float*)d_in[0];
    const float* t     = (const float*)d_in[1];
    const int*   ei    = (const int*)d_in[2];
    const int*   nmask = (const int*)d_in[3];
    const int*   emask = (const int*)d_in[4];
    const int*   ondp  = (const int*)d_in[5];
    const int*   oedp  = (const int*)d_in[6];
    const float* W1f   = (const float*)d_in[7];
    const float* b1f   = (const float*)d_in[8];
    const float* W2f   = (const float*)d_in[9];
    const float* b2f   = (const float*)d_in[10];
    const float* W1r   = (const float*)d_in[11];
    const float* b1r   = (const float*)d_in[12];
    const float* W2r   = (const float*)d_in[13];
    const float* b2r   = (const float*)d_in[14];
    const float* eps   = (const float*)d_in[15];
    const float* gam   = (const float*)d_in[16];
    const float* bet   = (const float*)d_in[17];
    const float* linW  = (const float*)d_in[18];
    const float* linb  = (const float*)d_in[19];
    float* out = (float*)d_out;

    const int* src = ei;
    const int* dst = ei + NE;

    // CSR build (4 launches)
    k_initcount<<<NE / 256, 256>>>(x, t, dst);
    k_scan1<<<256, 1024>>>();
    k_scan3<<<NN / 256, 256>>>();
    k_fill<<<NE / 256, 256>>>(src, dst);

    __half* h0p;  cudaGetSymbolAddress((void**)&h0p, g_h0);
    __half* hlp;  cudaGetSymbolAddress((void**)&hlp, g_hl);

    // layer 0 (padded K=12, h0 stride 16 halfs = 32B rows)
    k_gatherH<1, 16><<<(NN * 2) / 256, 256>>>(h0p);
    k_node<12, 9, 16><<<NN / 128, 128>>>(h0p, W1f, b1f, W2f, b2f, eps, 0);
    k_bn<<<(NN * 8) / 256, 256>>>(gam, bet, 0);

    // layers 1..2
    for (int l = 1; l < 3; l++) {
        const __half* hprev = hlp + (size_t)(l - 1) * NN * 32;
        k_gatherH<2, 32><<<(NN * 4) / 256, 256>>>(hprev);
        k_node<32, 32, 32><<<NN / 128, 128>>>(hprev,
                                              W1r + (l - 1) * 1024, b1r + (l - 1) * 32,
                                              W2r + (l - 1) * 1024, b2r + (l - 1) * 32,
                                              eps, l);
        k_bn<<<(NN * 8) / 256, 256>>>(gam, bet, l);
    }

    // layer 3: gather, node(+stats), then fused bn3+final
    {
        const __half* hprev = hlp + (size_t)2 * NN * 32;
        k_gatherH<2, 32><<<(NN * 4) / 256, 256>>>(hprev);
        k_node<32, 32, 32><<<NN / 128, 128>>>(hprev,
                                              W1r + 2 * 1024, b1r + 2 * 32,
                                              W2r + 2 * 1024, b2r + 2 * 32,
                                              eps, 3);
        k_bnfinal<<<NN / 128, 128>>>(x, gam, bet, linW, linb,
                                     nmask, emask, ondp, oedp, out);
    }
}